// round 1
// baseline (speedup 1.0000x reference)
#include <cuda_runtime.h>
#include <math.h>

// Problem constants
#define BB 8
#define CH 16
#define NX 64
#define NY 64
#define TT 64
#define MK 12          // kept t-modes
#define MX 24          // kept x-modes (12 low + 12 high)
#define MY 24          // kept y-modes
#define NFREQ (MX*MY*MK)   // 6912

// Scratch buffers (__device__ globals; reused across stages)
// BufA: [b,c, x, y, kt] (forward G1)  and [b,o, x, y, kt] (inverse H2)
// BufB: [b,c, x, kyi, kt] (forward G2) and [b,o, x, kyi, kt] (inverse H1)
__device__ float2 g_bufA[BB*CH*NX*NY*MK];     // 6,291,456 float2
__device__ float2 g_bufB[BB*CH*NX*MY*MK];     // 2,359,296 float2
__device__ float2 g_XF[BB*CH*NFREQ];          //   884,736 float2
__device__ float2 g_OF[BB*CH*NFREQ];          //   884,736 float2

__device__ __forceinline__ void tw_init(float2* tw, int tid) {
    if (tid < 64) {
        float s, c;
        sincospif((float)tid / 32.0f, &s, &c);   // angle = 2*pi*tid/64
        tw[tid] = make_float2(c, s);
    }
}

// ---------------------------------------------------------------------------
// K1: forward real DFT over t.  x[b,c,ix,iy,t] -> bufA[b,c,ix,iy,kt] (kt<12)
// One block handles 32 contiguous rows of 64 samples.
// ---------------------------------------------------------------------------
__global__ void k1_fft_t(const float* __restrict__ x) {
    __shared__ float s[32][65];
    __shared__ float2 tw[64];
    int tid = threadIdx.x;           // 384 threads
    tw_init(tw, tid);
    long base = (long)blockIdx.x * 32 * 64;
    for (int e = tid; e < 2048; e += 384)
        s[e >> 6][e & 63] = x[base + e];
    __syncthreads();

    int row = tid / MK;
    int kt  = tid % MK;
    float re = 0.f, im = 0.f;
    int idx = 0;
    #pragma unroll
    for (int t = 0; t < 64; t++) {
        float v = s[row][t];
        float2 w = tw[idx];
        re = fmaf(v, w.x, re);
        im = fmaf(-v, w.y, im);
        idx = (idx + kt) & 63;
    }
    g_bufA[(long)blockIdx.x * 384 + tid] = make_float2(re, im);
}

// ---------------------------------------------------------------------------
// K2: forward complex DFT over y.  bufA[b,c,ix, y,kt] -> bufB[b,c,ix, kyi,kt]
// One block per (b,c,ix).
// ---------------------------------------------------------------------------
__global__ void k2_fft_y() {
    __shared__ float2 s[NY * MK];    // 768
    __shared__ float2 tw[64];
    int tid = threadIdx.x;           // 288 threads
    tw_init(tw, tid);
    long base = (long)blockIdx.x * (NY * MK);
    for (int e = tid; e < NY * MK; e += 288)
        s[e] = g_bufA[base + e];
    __syncthreads();

    int kyi = tid / MK;
    int kt  = tid % MK;
    int ky = (kyi < 12) ? kyi : kyi + 40;     // {0..11, 52..63}
    float re = 0.f, im = 0.f;
    int idx = 0;
    #pragma unroll 8
    for (int y = 0; y < 64; y++) {
        float2 v = s[y * MK + kt];
        float2 w = tw[idx];
        // v * (cos - i sin)
        re += v.x * w.x + v.y * w.y;
        im += v.y * w.x - v.x * w.y;
        idx = (idx + ky) & 63;
    }
    g_bufB[(long)blockIdx.x * (MY * MK) + tid] = make_float2(re, im);
}

// ---------------------------------------------------------------------------
// K3: forward complex DFT over x.  bufB[b,c,x,kyi,kt] -> XF[b,c,kxi,kyi,kt]
// One block per (bc, kyi).
// ---------------------------------------------------------------------------
__global__ void k3_fft_x() {
    __shared__ float2 s[NX * MK];    // 768
    __shared__ float2 tw[64];
    int tid = threadIdx.x;           // 288 threads
    int bc  = blockIdx.x / MY;
    int kyi = blockIdx.x % MY;
    tw_init(tw, tid);
    for (int e = tid; e < NX * MK; e += 288) {
        int ix = e / MK, kt = e % MK;
        s[e] = g_bufB[((long)bc * NX + ix) * (MY * MK) + kyi * MK + kt];
    }
    __syncthreads();

    int kxi = tid / MK;
    int kt  = tid % MK;
    int kx = (kxi < 12) ? kxi : kxi + 40;
    float re = 0.f, im = 0.f;
    int idx = 0;
    #pragma unroll 8
    for (int ix = 0; ix < 64; ix++) {
        float2 v = s[ix * MK + kt];
        float2 w = tw[idx];
        re += v.x * w.x + v.y * w.y;
        im += v.y * w.x - v.x * w.y;
        idx = (idx + kx) & 63;
    }
    g_XF[(((long)bc * MX + kxi) * MY + kyi) * MK + kt] = make_float2(re, im);
}

// ---------------------------------------------------------------------------
// K4: complex channel mix per frequency. XF[b,i,f] -> OF[b,o,f]
// One block per frequency f (6912 blocks).
// ---------------------------------------------------------------------------
__global__ void k4_mix(const float* __restrict__ w1, const float* __restrict__ w2,
                       const float* __restrict__ w3, const float* __restrict__ w4) {
    int f = blockIdx.x;
    int kxi = f / (MY * MK);
    int kyi = (f / MK) % MY;
    int kt  = f % MK;
    const float* w = (kxi < 12) ? ((kyi < 12) ? w1 : w3)
                                : ((kyi < 12) ? w2 : w4);
    int kxp = kxi % 12, kyp = kyi % 12;

    __shared__ float2 ws[16][16];
    __shared__ float2 xs[8][16];
    int tid = threadIdx.x;           // 256 threads
    {
        int i = tid / 16, o = tid % 16;
        long wi = ((((long)i * 16 + o) * 12 + kxp) * 12 + kyp) * 12 + kt;
        ws[i][o] = make_float2(w[wi * 2], w[wi * 2 + 1]);
    }
    if (tid < 128) {
        int b = tid / 16, i = tid % 16;
        xs[b][i] = g_XF[(long)(b * 16 + i) * NFREQ + f];
    }
    __syncthreads();
    if (tid < 128) {
        int b = tid / 16, o = tid % 16;
        float re = 0.f, im = 0.f;
        #pragma unroll
        for (int i = 0; i < 16; i++) {
            float2 a = xs[b][i];
            float2 wv = ws[i][o];
            re += a.x * wv.x - a.y * wv.y;
            im += a.x * wv.y + a.y * wv.x;
        }
        g_OF[(long)(b * 16 + o) * NFREQ + f] = make_float2(re, im);
    }
}

// ---------------------------------------------------------------------------
// K5: inverse complex DFT over x. OF[b,o,kxi,kyi,kt] -> bufB[b,o,ix,kyi,kt]
// One block per (bo, kyi).
// ---------------------------------------------------------------------------
__global__ void k5_ifft_x() {
    __shared__ float2 s[MX * MK];    // 288
    __shared__ float2 tw[64];
    int tid = threadIdx.x;           // 256 threads
    int bo  = blockIdx.x / MY;
    int kyi = blockIdx.x % MY;
    tw_init(tw, tid);
    for (int e = tid; e < MX * MK; e += 256) {
        int kxi = e / MK, kt = e % MK;
        s[e] = g_OF[(((long)bo * MX + kxi) * MY + kyi) * MK + kt];
    }
    __syncthreads();

    for (int j = tid; j < NX * MK; j += 256) {
        int ix = j / MK, kt = j % MK;
        float re = 0.f, im = 0.f;
        #pragma unroll
        for (int kxi = 0; kxi < MX; kxi++) {
            int kx = (kxi < 12) ? kxi : kxi + 40;
            float2 v = s[kxi * MK + kt];
            float2 w = tw[(kx * ix) & 63];
            // v * (cos + i sin)
            re += v.x * w.x - v.y * w.y;
            im += v.x * w.y + v.y * w.x;
        }
        g_bufB[(((long)bo * NX + ix) * MY + kyi) * MK + kt] = make_float2(re, im);
    }
}

// ---------------------------------------------------------------------------
// K6: inverse complex DFT over y. bufB[b,o,ix,kyi,kt] -> bufA[b,o,ix,iy,kt]
// One block per (bo, ix).
// ---------------------------------------------------------------------------
__global__ void k6_ifft_y() {
    __shared__ float2 s[MY * MK];    // 288
    __shared__ float2 tw[64];
    int tid = threadIdx.x;           // 256 threads
    tw_init(tw, tid);
    long base = (long)blockIdx.x * (MY * MK);
    for (int e = tid; e < MY * MK; e += 256)
        s[e] = g_bufB[base + e];
    __syncthreads();

    for (int j = tid; j < NY * MK; j += 256) {
        int iy = j / MK, kt = j % MK;
        float re = 0.f, im = 0.f;
        #pragma unroll
        for (int kyi = 0; kyi < MY; kyi++) {
            int ky = (kyi < 12) ? kyi : kyi + 40;
            float2 v = s[kyi * MK + kt];
            float2 w = tw[(ky * iy) & 63];
            re += v.x * w.x - v.y * w.y;
            im += v.x * w.y + v.y * w.x;
        }
        g_bufA[(long)blockIdx.x * (NY * MK) + j] = make_float2(re, im);
    }
}

// ---------------------------------------------------------------------------
// K7: inverse real DFT over t (Hermitian, numpy irfft semantics: DC imag
// discarded, k>=1 doubled, modes 12..32 zero), scale 1/64^3, ReLU,
// channel mix with lo_w, add bias, write output.
// One block per (b, ix, iy); 64 threads = one t each.
// ---------------------------------------------------------------------------
__global__ void k7_final(const float* __restrict__ lo_w,
                         const float* __restrict__ lo_b,
                         float* __restrict__ out) {
    __shared__ float2 F[16][MK];
    __shared__ float lw[16][16];
    __shared__ float lb[16];
    __shared__ float2 tw[64];
    int tid = threadIdx.x;           // 64 threads
    int b  = blockIdx.x >> 12;
    int xy = blockIdx.x & 4095;
    tw_init(tw, tid);
    for (int e = tid; e < 16 * MK; e += 64) {
        int c = e / MK, kt = e % MK;
        F[c][kt] = g_bufA[((long)(b * 16 + c) * 4096 + xy) * MK + kt];
    }
    for (int e = tid; e < 256; e += 64) lw[e / 16][e % 16] = lo_w[e];
    if (tid < 16) lb[tid] = lo_b[tid];
    __syncthreads();

    int t = tid;
    // precompute 2*cos / 2*sin for this t
    float c2[MK], s2[MK];
    #pragma unroll
    for (int k = 1; k < MK; k++) {
        float2 w = tw[(k * t) & 63];
        c2[k] = 2.0f * w.x;
        s2[k] = 2.0f * w.y;
    }

    float acc[16];
    #pragma unroll
    for (int o = 0; o < 16; o++) acc[o] = lb[o];

    const float scale = 1.0f / (64.0f * 64.0f * 64.0f);
    #pragma unroll
    for (int c = 0; c < 16; c++) {
        float v = F[c][0].x;            // DC: real part only
        #pragma unroll
        for (int k = 1; k < MK; k++) {
            float2 fv = F[c][k];
            v += fv.x * c2[k] - fv.y * s2[k];
        }
        v *= scale;
        v = fmaxf(v, 0.0f);
        #pragma unroll
        for (int o = 0; o < 16; o++)
            acc[o] = fmaf(lw[o][c], v, acc[o]);
    }

    long obase = (long)b * 16 * 262144 + (long)xy * 64 + t;
    #pragma unroll
    for (int o = 0; o < 16; o++)
        out[obase + (long)o * 262144] = acc[o];
}

// ---------------------------------------------------------------------------
extern "C" void kernel_launch(void* const* d_in, const int* in_sizes, int n_in,
                              void* d_out, int out_size) {
    const float* x    = (const float*)d_in[0];
    const float* w1   = (const float*)d_in[1];
    const float* w2   = (const float*)d_in[2];
    const float* w3   = (const float*)d_in[3];
    const float* w4   = (const float*)d_in[4];
    const float* lo_w = (const float*)d_in[5];
    const float* lo_b = (const float*)d_in[6];
    float* out = (float*)d_out;

    k1_fft_t<<<(BB*CH*NX*NY)/32, 384>>>(x);
    k2_fft_y<<<BB*CH*NX, 288>>>();
    k3_fft_x<<<BB*CH*MY, 288>>>();
    k4_mix<<<NFREQ, 256>>>(w1, w2, w3, w4);
    k5_ifft_x<<<BB*CH*MY, 256>>>();
    k6_ifft_y<<<BB*CH*NX, 256>>>();
    k7_final<<<BB*NX*NY, 64>>>(lo_w, lo_b, out);
}

// round 3
// speedup vs baseline: 1.6264x; 1.6264x over previous
#include <cuda_runtime.h>
#include <math.h>

#define BB 8
#define CH 16
#define NX 64
#define NY 64
#define TT 64
#define MK 12          // kept t-modes
#define MX 24          // kept x-modes
#define MY 24          // kept y-modes
#define NFREQ (MX*MY*MK)   // 6912

// Scratch (__device__ globals, reused across stages)
__device__ float2 g_bufA[BB*CH*NX*NY*MK];   // [b,c,ix,iy,kt] fwd / [b,o,ix,iy,kt] inv
__device__ float2 g_bufB[BB*CH*NX*MY*MK];   // [b,c,ix,kyi,kt] fwd / [b,o,ix,kyi,kt] inv
__device__ float2 g_XF[BB*CH*NFREQ];
__device__ float2 g_OF[BB*CH*NFREQ];

// ---------------------------------------------------------------------------
// K1: real t-DFT, 64 -> 12 modes. 1 thread = 1 row, 12 complex accums in regs.
// twm[t][k] = (cos(2*pi*k*t/64), -sin(...)) read as lane-uniform float4.
// ---------------------------------------------------------------------------
__global__ void k1_fft_t(const float* __restrict__ x) {
    __shared__ float s[128][65];
    __shared__ float2 twm[64*12];
    int tid = threadIdx.x;  // 128
    for (int e = tid; e < 768; e += 128) {
        int t = e / 12, k = e % 12;
        float sn, cs;
        sincospif((float)((t * k) & 63) / 32.0f, &sn, &cs);
        twm[e] = make_float2(cs, -sn);
    }
    long base = (long)blockIdx.x * 128 * 64;
    const float4* xv = (const float4*)(x + base);
    for (int e = tid; e < 2048; e += 128) {
        float4 v = xv[e];
        int row = e >> 4, col = (e & 15) << 2;
        s[row][col] = v.x; s[row][col+1] = v.y; s[row][col+2] = v.z; s[row][col+3] = v.w;
    }
    __syncthreads();

    float ac[24];
    #pragma unroll
    for (int i = 0; i < 24; i++) ac[i] = 0.f;

    for (int t = 0; t < 64; t++) {
        float v = s[tid][t];
        const float4* tp = (const float4*)&twm[t * 12];
        #pragma unroll
        for (int j = 0; j < 6; j++) {
            float4 w = tp[j];
            ac[4*j]   = fmaf(v, w.x, ac[4*j]);
            ac[4*j+1] = fmaf(v, w.y, ac[4*j+1]);
            ac[4*j+2] = fmaf(v, w.z, ac[4*j+2]);
            ac[4*j+3] = fmaf(v, w.w, ac[4*j+3]);
        }
    }
    float4* ob = (float4*)&g_bufA[((long)blockIdx.x * 128 + tid) * 12];
    #pragma unroll
    for (int j = 0; j < 6; j++)
        ob[j] = make_float4(ac[4*j], ac[4*j+1], ac[4*j+2], ac[4*j+3]);
}

// ---------------------------------------------------------------------------
// K2: complex y-DFT, 64 -> 24 modes (12 low + 12 high via conjugate).
// Block = (b,c, 8 ix), 96 threads = (ixl, kt). 24 complex accums/thread.
// tw2[y][m] (m=0..12, padded to 14) = (cos(2*pi*m*y/64), -sin(...)).
// ---------------------------------------------------------------------------
__global__ void k2_fft_y() {
    __shared__ float2 sIn[8 * 16 * 12];     // one y-chunk of 16
    __shared__ float2 tw2[64 * 14];
    int tid = threadIdx.x;  // 96
    for (int e = tid; e < 64 * 13; e += 96) {
        int y = e / 13, m = e % 13;
        float sn, cs;
        sincospif((float)((y * m) & 63) / 32.0f, &sn, &cs);
        tw2[y * 14 + m] = make_float2(cs, -sn);
    }
    int bc  = blockIdx.x >> 3;
    int ixg = (blockIdx.x & 7) * 8;
    int ixl = tid / 12, kt = tid % 12;

    float ar[24], ai[24];
    #pragma unroll
    for (int i = 0; i < 24; i++) { ar[i] = 0.f; ai[i] = 0.f; }

    for (int cy = 0; cy < 4; cy++) {
        __syncthreads();
        for (int e = tid; e < 768; e += 96) {
            int il = e / 96, r = e % 96;
            const float4* src = (const float4*)&g_bufA[(((long)(bc * 64 + ixg + il) * 64) + cy * 16) * 12];
            ((float4*)sIn)[il * 96 + r] = src[r];
        }
        __syncthreads();
        for (int yy = 0; yy < 16; yy++) {
            int y = cy * 16 + yy;
            float2 v = sIn[ixl * 192 + yy * 12 + kt];
            const float4* tp = (const float4*)&tw2[y * 14];
            float wr[13], wi[13];
            float4 q;
            q = tp[0]; wr[0]=q.x; wi[0]=q.y; wr[1]=q.z; wi[1]=q.w;
            q = tp[1]; wr[2]=q.x; wi[2]=q.y; wr[3]=q.z; wi[3]=q.w;
            q = tp[2]; wr[4]=q.x; wi[4]=q.y; wr[5]=q.z; wi[5]=q.w;
            q = tp[3]; wr[6]=q.x; wi[6]=q.y; wr[7]=q.z; wi[7]=q.w;
            q = tp[4]; wr[8]=q.x; wi[8]=q.y; wr[9]=q.z; wi[9]=q.w;
            q = tp[5]; wr[10]=q.x; wi[10]=q.y; wr[11]=q.z; wi[11]=q.w;
            q = tp[6]; wr[12]=q.x; wi[12]=q.y;
            #pragma unroll
            for (int m = 0; m < 12; m++) {
                ar[m] = fmaf(v.x, wr[m], fmaf(-v.y, wi[m], ar[m]));
                ai[m] = fmaf(v.x, wi[m], fmaf( v.y, wr[m], ai[m]));
            }
            #pragma unroll
            for (int j = 0; j < 12; j++) {
                int m = 12 - j;  // conj multiplier
                ar[12+j] = fmaf(v.x, wr[m], fmaf( v.y, wi[m], ar[12+j]));
                ai[12+j] = fmaf(v.y, wr[m], fmaf(-v.x, wi[m], ai[12+j]));
            }
        }
    }
    long obase = ((long)(bc * 64 + ixg + ixl) * 24) * 12 + kt;
    #pragma unroll
    for (int kyi = 0; kyi < 24; kyi++)
        g_bufB[obase + kyi * 12] = make_float2(ar[kyi], ai[kyi]);
}

// ---------------------------------------------------------------------------
// K3: complex x-DFT, 64 -> 24 modes. Block = (b,c), 288 threads = (kyi,kt).
// ---------------------------------------------------------------------------
__global__ void k3_fft_x() {
    __shared__ float2 sIn[16 * 288];        // one ix-chunk of 16
    __shared__ float2 tw2[64 * 14];
    int tid = threadIdx.x;  // 288
    for (int e = tid; e < 64 * 13; e += 288) {
        int t = e / 13, m = e % 13;
        float sn, cs;
        sincospif((float)((t * m) & 63) / 32.0f, &sn, &cs);
        tw2[t * 14 + m] = make_float2(cs, -sn);
    }
    int bc = blockIdx.x;

    float ar[24], ai[24];
    #pragma unroll
    for (int i = 0; i < 24; i++) { ar[i] = 0.f; ai[i] = 0.f; }

    for (int cx = 0; cx < 4; cx++) {
        __syncthreads();
        {
            const float4* src = (const float4*)&g_bufB[((long)(bc * 64 + cx * 16)) * 288];
            for (int e = tid; e < 2304; e += 288)
                ((float4*)sIn)[e] = src[e];
        }
        __syncthreads();
        for (int ixl = 0; ixl < 16; ixl++) {
            int ix = cx * 16 + ixl;
            float2 v = sIn[ixl * 288 + tid];
            const float4* tp = (const float4*)&tw2[ix * 14];
            float wr[13], wi[13];
            float4 q;
            q = tp[0]; wr[0]=q.x; wi[0]=q.y; wr[1]=q.z; wi[1]=q.w;
            q = tp[1]; wr[2]=q.x; wi[2]=q.y; wr[3]=q.z; wi[3]=q.w;
            q = tp[2]; wr[4]=q.x; wi[4]=q.y; wr[5]=q.z; wi[5]=q.w;
            q = tp[3]; wr[6]=q.x; wi[6]=q.y; wr[7]=q.z; wi[7]=q.w;
            q = tp[4]; wr[8]=q.x; wi[8]=q.y; wr[9]=q.z; wi[9]=q.w;
            q = tp[5]; wr[10]=q.x; wi[10]=q.y; wr[11]=q.z; wi[11]=q.w;
            q = tp[6]; wr[12]=q.x; wi[12]=q.y;
            #pragma unroll
            for (int m = 0; m < 12; m++) {
                ar[m] = fmaf(v.x, wr[m], fmaf(-v.y, wi[m], ar[m]));
                ai[m] = fmaf(v.x, wi[m], fmaf( v.y, wr[m], ai[m]));
            }
            #pragma unroll
            for (int j = 0; j < 12; j++) {
                int m = 12 - j;
                ar[12+j] = fmaf(v.x, wr[m], fmaf( v.y, wi[m], ar[12+j]));
                ai[12+j] = fmaf(v.y, wr[m], fmaf(-v.x, wi[m], ai[12+j]));
            }
        }
    }
    long obase = (long)bc * NFREQ + tid;   // tid = kyi*12+kt
    #pragma unroll
    for (int kxi = 0; kxi < 24; kxi++)
        g_XF[obase + kxi * 288] = make_float2(ar[kxi], ai[kxi]);
}

// ---------------------------------------------------------------------------
// K4: per-frequency 16x16 complex channel mix. 4 freqs/block, 512 threads.
// ---------------------------------------------------------------------------
__global__ void k4_mix(const float* __restrict__ w1, const float* __restrict__ w2,
                       const float* __restrict__ w3, const float* __restrict__ w4) {
    __shared__ float2 ws[4][256];
    __shared__ float2 xs[4][128];
    int tid  = threadIdx.x;            // 512
    int slot = tid >> 7, st = tid & 127;
    int f = blockIdx.x * 4 + slot;
    int kxi = f / 288, kyi = (f / 12) % 24, kt = f % 12;
    const float* w = (kxi < 12) ? ((kyi < 12) ? w1 : w3)
                                : ((kyi < 12) ? w2 : w4);
    int kxp = kxi % 12, kyp = kyi % 12;
    long wbase = ((long)kxp * 12 + kyp) * 12 + kt;
    #pragma unroll
    for (int r = 0; r < 2; r++) {
        int e = st + r * 128;          // e = i*16+o
        const float2* wp = (const float2*)(w) + (long)e * 1728 + wbase;
        ws[slot][e] = *wp;
    }
    {
        int b = st >> 4, i = st & 15;
        xs[slot][st] = g_XF[(long)(b * 16 + i) * NFREQ + f];
    }
    __syncthreads();
    int b = st >> 4, o = st & 15;
    float re = 0.f, im = 0.f;
    #pragma unroll
    for (int i = 0; i < 16; i++) {
        float2 a  = xs[slot][b * 16 + i];
        float2 wv = ws[slot][i * 16 + o];
        re = fmaf(a.x, wv.x, fmaf(-a.y, wv.y, re));
        im = fmaf(a.x, wv.y, fmaf( a.y, wv.x, im));
    }
    g_OF[(long)(b * 16 + o) * NFREQ + f] = make_float2(re, im);
}

// ---------------------------------------------------------------------------
// K5: inverse x-DFT, 24 -> 64. Block = (bo, 4 kyi), 256 threads = (kslot, ix).
// Data broadcast per (kxi,kt); twiddle per-lane. 12 complex accums.
// ---------------------------------------------------------------------------
__global__ void k5_ifft_x() {
    __shared__ float2 sIn[4 * 288];
    __shared__ float2 tw[64];
    int tid = threadIdx.x;  // 256
    if (tid < 64) {
        float sn, cs; sincospif((float)tid / 32.0f, &sn, &cs);
        tw[tid] = make_float2(cs, sn);
    }
    int bo  = blockIdx.x / 6;
    int kyg = (blockIdx.x % 6) * 4;
    for (int e = tid; e < 1152; e += 256) {
        int ks = e / 288, r = e % 288, kxi = r / 12, ktl = r % 12;
        sIn[e] = g_OF[((long)(bo * 24 + kxi) * 24 + kyg + ks) * 12 + ktl];
    }
    __syncthreads();
    int kslot = tid >> 6, ix = tid & 63;

    float ar[12], ai[12];
    #pragma unroll
    for (int i = 0; i < 12; i++) { ar[i] = 0.f; ai[i] = 0.f; }

    #pragma unroll
    for (int kxi = 0; kxi < 24; kxi++) {
        int kx = (kxi < 12) ? kxi : kxi + 40;
        float2 w = tw[(kx * ix) & 63];
        const float4* sp = (const float4*)&sIn[kslot * 288 + kxi * 12];
        #pragma unroll
        for (int j = 0; j < 6; j++) {
            float4 v = sp[j];
            ar[2*j]   = fmaf(v.x, w.x, fmaf(-v.y, w.y, ar[2*j]));
            ai[2*j]   = fmaf(v.x, w.y, fmaf( v.y, w.x, ai[2*j]));
            ar[2*j+1] = fmaf(v.z, w.x, fmaf(-v.w, w.y, ar[2*j+1]));
            ai[2*j+1] = fmaf(v.z, w.y, fmaf( v.w, w.x, ai[2*j+1]));
        }
    }
    float4* ob = (float4*)&g_bufB[((long)(bo * 64 + ix) * 24 + kyg + kslot) * 12];
    #pragma unroll
    for (int j = 0; j < 6; j++)
        ob[j] = make_float4(ar[2*j], ai[2*j], ar[2*j+1], ai[2*j+1]);
}

// ---------------------------------------------------------------------------
// K6: inverse y-DFT, 24 -> 64. Block = (bo, 4 ix), 256 threads = (ixslot, iy).
// ---------------------------------------------------------------------------
__global__ void k6_ifft_y() {
    __shared__ float2 sIn[4 * 288];
    __shared__ float2 tw[64];
    int tid = threadIdx.x;  // 256
    if (tid < 64) {
        float sn, cs; sincospif((float)tid / 32.0f, &sn, &cs);
        tw[tid] = make_float2(cs, sn);
    }
    int bo  = blockIdx.x >> 4;
    int ixg = (blockIdx.x & 15) * 4;
    for (int e = tid; e < 576; e += 256) {
        int is = e / 144, r = e % 144;
        const float4* src = (const float4*)&g_bufB[((long)(bo * 64 + ixg + is) * 24) * 12];
        ((float4*)sIn)[is * 144 + r] = src[r];
    }
    __syncthreads();
    int ixslot = tid >> 6, iy = tid & 63;

    float ar[12], ai[12];
    #pragma unroll
    for (int i = 0; i < 12; i++) { ar[i] = 0.f; ai[i] = 0.f; }

    #pragma unroll
    for (int kyi = 0; kyi < 24; kyi++) {
        int ky = (kyi < 12) ? kyi : kyi + 40;
        float2 w = tw[(ky * iy) & 63];
        const float4* sp = (const float4*)&sIn[ixslot * 288 + kyi * 12];
        #pragma unroll
        for (int j = 0; j < 6; j++) {
            float4 v = sp[j];
            ar[2*j]   = fmaf(v.x, w.x, fmaf(-v.y, w.y, ar[2*j]));
            ai[2*j]   = fmaf(v.x, w.y, fmaf( v.y, w.x, ai[2*j]));
            ar[2*j+1] = fmaf(v.z, w.x, fmaf(-v.w, w.y, ar[2*j+1]));
            ai[2*j+1] = fmaf(v.z, w.y, fmaf( v.w, w.x, ai[2*j+1]));
        }
    }
    float4* ob = (float4*)&g_bufA[((long)(bo * 64 + ixg + ixslot) * 64 + iy) * 12];
    #pragma unroll
    for (int j = 0; j < 6; j++)
        ob[j] = make_float4(ar[2*j], ai[2*j], ar[2*j+1], ai[2*j+1]);
}

// ---------------------------------------------------------------------------
// K7: inverse real t-DFT (hermitian, k>=1 doubled) + 1/64^3 + ReLU +
// 16x16 channel mix + bias. Block = 4 xy-points x 64 t = 256 threads.
// ---------------------------------------------------------------------------
__global__ void k7_final(const float* __restrict__ lo_w,
                         const float* __restrict__ lo_b,
                         float* __restrict__ out) {
    __shared__ float2 F[4 * 16 * 12];
    __shared__ float  lwT[256];   // [c][o]
    __shared__ float  lb[16];
    __shared__ float2 tw[64];
    int tid = threadIdx.x;  // 256
    if (tid < 64) {
        float sn, cs; sincospif((float)tid / 32.0f, &sn, &cs);
        tw[tid] = make_float2(cs, sn);
    }
    if (tid < 256) lwT[tid] = lo_w[(tid & 15) * 16 + (tid >> 4)];
    if (tid < 16)  lb[tid]  = lo_b[tid];

    int b   = blockIdx.x >> 10;
    int xy0 = (blockIdx.x & 1023) * 4;
    for (int e = tid; e < 384; e += 256) {
        int slot = e / 96, c = (e % 96) / 6, j = e % 6;
        const float4* src = (const float4*)g_bufA + ((long)(b * 16 + c) * 4096 + xy0 + slot) * 6 + j;
        ((float4*)F)[slot * 96 + c * 6 + j] = *src;
    }
    __syncthreads();

    int slot = tid >> 6, t = tid & 63;
    int xy = xy0 + slot;

    float c2[12], s2[12];
    #pragma unroll
    for (int k = 1; k < 12; k++) {
        float2 w = tw[(k * t) & 63];
        c2[k] = 2.0f * w.x;
        s2[k] = 2.0f * w.y;
    }

    float acc[16];
    #pragma unroll
    for (int o = 0; o < 16; o++) acc[o] = lb[o];

    const float scale = 1.0f / (64.0f * 64.0f * 64.0f);
    #pragma unroll 4
    for (int c = 0; c < 16; c++) {
        const float4* Fp = (const float4*)&F[slot * 192 + c * 12];
        float4 a0 = Fp[0], a1 = Fp[1], a2 = Fp[2], a3 = Fp[3], a4 = Fp[4], a5 = Fp[5];
        float v = a0.x;
        v = fmaf(a0.z, c2[1],  fmaf(-a0.w, s2[1],  v));
        v = fmaf(a1.x, c2[2],  fmaf(-a1.y, s2[2],  v));
        v = fmaf(a1.z, c2[3],  fmaf(-a1.w, s2[3],  v));
        v = fmaf(a2.x, c2[4],  fmaf(-a2.y, s2[4],  v));
        v = fmaf(a2.z, c2[5],  fmaf(-a2.w, s2[5],  v));
        v = fmaf(a3.x, c2[6],  fmaf(-a3.y, s2[6],  v));
        v = fmaf(a3.z, c2[7],  fmaf(-a3.w, s2[7],  v));
        v = fmaf(a4.x, c2[8],  fmaf(-a4.y, s2[8],  v));
        v = fmaf(a4.z, c2[9],  fmaf(-a4.w, s2[9],  v));
        v = fmaf(a5.x, c2[10], fmaf(-a5.y, s2[10], v));
        v = fmaf(a5.z, c2[11], fmaf(-a5.w, s2[11], v));
        v = fmaxf(v * scale, 0.0f);
        const float4* lp = (const float4*)&lwT[c * 16];
        float4 l0 = lp[0], l1 = lp[1], l2 = lp[2], l3 = lp[3];
        acc[0]  = fmaf(l0.x, v, acc[0]);  acc[1]  = fmaf(l0.y, v, acc[1]);
        acc[2]  = fmaf(l0.z, v, acc[2]);  acc[3]  = fmaf(l0.w, v, acc[3]);
        acc[4]  = fmaf(l1.x, v, acc[4]);  acc[5]  = fmaf(l1.y, v, acc[5]);
        acc[6]  = fmaf(l1.z, v, acc[6]);  acc[7]  = fmaf(l1.w, v, acc[7]);
        acc[8]  = fmaf(l2.x, v, acc[8]);  acc[9]  = fmaf(l2.y, v, acc[9]);
        acc[10] = fmaf(l2.z, v, acc[10]); acc[11] = fmaf(l2.w, v, acc[11]);
        acc[12] = fmaf(l3.x, v, acc[12]); acc[13] = fmaf(l3.y, v, acc[13]);
        acc[14] = fmaf(l3.z, v, acc[14]); acc[15] = fmaf(l3.w, v, acc[15]);
    }

    long obase = ((long)(b * 16) * 4096 + xy) * 64 + t;
    #pragma unroll
    for (int o = 0; o < 16; o++)
        out[obase + (long)o * 262144] = acc[o];
}

// ---------------------------------------------------------------------------
extern "C" void kernel_launch(void* const* d_in, const int* in_sizes, int n_in,
                              void* d_out, int out_size) {
    const float* x    = (const float*)d_in[0];
    const float* w1   = (const float*)d_in[1];
    const float* w2   = (const float*)d_in[2];
    const float* w3   = (const float*)d_in[3];
    const float* w4   = (const float*)d_in[4];
    const float* lo_w = (const float*)d_in[5];
    const float* lo_b = (const float*)d_in[6];
    float* out = (float*)d_out;

    k1_fft_t<<<4096, 128>>>(x);
    k2_fft_y<<<1024, 96>>>();
    k3_fft_x<<<128, 288>>>();
    k4_mix<<<1728, 512>>>(w1, w2, w3, w4);
    k5_ifft_x<<<768, 256>>>();
    k6_ifft_y<<<2048, 256>>>();
    k7_final<<<8192, 256>>>(lo_w, lo_b, out);
}